// round 1
// baseline (speedup 1.0000x reference)
#include <cuda_runtime.h>
#include <math.h>

#define B_    4
#define CIN_  256
#define N_    4096
#define HEADS_ 4
#define DH_   32
#define HID_  128
#define OQKV_ 384

// Scratch (allocation-free rule: __device__ globals)
__device__ float g_qkv[B_ * OQKV_ * N_];    // [b][o][n], o: q=0..127, k=128..255, v=256..383
__device__ float g_scale[B_ * HID_];        // c[b][h*32+d] = 10 / (||q_d|| * ||k_d||)
__device__ float g_oimg[B_ * HID_ * N_];    // attention output, channel-major

// ---------------------------------------------------------------------------
// Batched GEMM: out[b][m][n] = sum_k W[m][k] * X[b][k][n] (+ bias[m])
// 64x64 block tile, K-step 16, 256 threads, 4x4 microtile.
// ---------------------------------------------------------------------------
__global__ void __launch_bounds__(256) gemm_wx(
    const float* __restrict__ W, const float* __restrict__ X,
    const float* __restrict__ bias, float* __restrict__ out,
    int M, int K, int N)
{
    __shared__ float As[16][68];   // [k][m]
    __shared__ float Bs[16][68];   // [k][n]

    const int b  = blockIdx.z;
    const int m0 = blockIdx.y * 64;
    const int n0 = blockIdx.x * 64;
    const int tid = threadIdx.x;
    const int ty = tid >> 4, tx = tid & 15;

    const float* Xb = X + (size_t)b * K * N;

    float acc[4][4] = {};

    for (int k0 = 0; k0 < K; k0 += 16) {
        // load W tile 64(m) x 16(k)
        #pragma unroll
        for (int t = tid; t < 64 * 16; t += 256) {
            int m = t >> 4, k = t & 15;
            As[k][m] = W[(size_t)(m0 + m) * K + k0 + k];
        }
        // load X tile 16(k) x 64(n) (coalesced over n)
        #pragma unroll
        for (int t = tid; t < 16 * 64; t += 256) {
            int k = t >> 6, n = t & 63;
            Bs[k][n] = Xb[(size_t)(k0 + k) * N + n0 + n];
        }
        __syncthreads();
        #pragma unroll
        for (int k = 0; k < 16; k++) {
            float4 a4 = *(const float4*)&As[k][ty * 4];
            float4 b4 = *(const float4*)&Bs[k][tx * 4];
            float av[4] = {a4.x, a4.y, a4.z, a4.w};
            float bv[4] = {b4.x, b4.y, b4.z, b4.w};
            #pragma unroll
            for (int i = 0; i < 4; i++)
                #pragma unroll
                for (int j = 0; j < 4; j++)
                    acc[i][j] += av[i] * bv[j];
        }
        __syncthreads();
    }

    #pragma unroll
    for (int i = 0; i < 4; i++) {
        int m = m0 + ty * 4 + i;
        float bv = bias ? bias[m] : 0.0f;
        float4 o4;
        o4.x = acc[i][0] + bv; o4.y = acc[i][1] + bv;
        o4.z = acc[i][2] + bv; o4.w = acc[i][3] + bv;
        *(float4*)(out + ((size_t)b * M + m) * N + n0 + tx * 4) = o4;
    }
}

// ---------------------------------------------------------------------------
// Per (b, h, d) row norms of q and k over n; fold l2norm + SCALE into c[d].
// grid = 512 blocks (b*128 + hd), 256 threads.
// ---------------------------------------------------------------------------
__global__ void __launch_bounds__(256) norm_kernel()
{
    const int idx = blockIdx.x;        // b*128 + hd
    const int b  = idx >> 7;
    const int hd = idx & 127;
    const float* q = g_qkv + ((size_t)(b * OQKV_ + hd)) * N_;
    const float* k = q + (size_t)HID_ * N_;

    float sq = 0.f, sk = 0.f;
    for (int i = threadIdx.x; i < N_; i += 256) {
        float a = q[i]; sq += a * a;
        float c = k[i]; sk += c * c;
    }
    __shared__ float rq[256], rk[256];
    rq[threadIdx.x] = sq; rk[threadIdx.x] = sk;
    __syncthreads();
    for (int s = 128; s > 0; s >>= 1) {
        if (threadIdx.x < s) {
            rq[threadIdx.x] += rq[threadIdx.x + s];
            rk[threadIdx.x] += rk[threadIdx.x + s];
        }
        __syncthreads();
    }
    if (threadIdx.x == 0) {
        float nq = fmaxf(sqrtf(rq[0]), 1e-12f);
        float nk = fmaxf(sqrtf(rk[0]), 1e-12f);
        g_scale[idx] = 10.0f / (nq * nk);
    }
}

// ---------------------------------------------------------------------------
// Flash-style attention. grid = (32 i-tiles, 16 bh), 128 threads.
// One thread owns one query row i: q[32] and acc[32] in registers.
// K',V tiles (128 j x 32 d, pitch 36) staged in smem in [j][d] layout so the
// inner loops are uniform-address (broadcast) LDS.128 + FFMA.
// Logits |s| ~ 0.05 (unit-row q,k, 32-dim dot, x10) -> exp without max shift
// is exact; softmax ratio is shift-invariant so result == reference.
// ---------------------------------------------------------------------------
__global__ void __launch_bounds__(128, 4) attn_kernel()
{
    __shared__ float ks[128][36];
    __shared__ float vs[128][36];
    __shared__ float cs[DH_];

    const int bh = blockIdx.y;
    const int b = bh >> 2, h = bh & 3;
    const int tid = threadIdx.x;
    const int i = blockIdx.x * 128 + tid;

    const float* qb = g_qkv + ((size_t)(b * OQKV_) + h * DH_) * N_;
    const float* kb = qb + (size_t)HID_ * N_;
    const float* vb = qb + (size_t)(2 * HID_) * N_;

    if (tid < DH_) cs[tid] = g_scale[(b * HEADS_ + h) * DH_ + tid];

    float q[DH_], acc[DH_];
    #pragma unroll
    for (int d = 0; d < DH_; d++) {
        q[d] = qb[(size_t)d * N_ + i];
        acc[d] = 0.0f;
    }
    float l = 0.0f;
    __syncthreads();

    for (int jt = 0; jt < N_; jt += 128) {
        #pragma unroll
        for (int d = 0; d < DH_; d++) {
            ks[tid][d] = kb[(size_t)d * N_ + jt + tid] * cs[d];
            vs[tid][d] = vb[(size_t)d * N_ + jt + tid];
        }
        __syncthreads();

        #pragma unroll 4
        for (int j = 0; j < 128; j++) {
            const float4* kr = (const float4*)&ks[j][0];
            float s = 0.0f;
            #pragma unroll
            for (int u = 0; u < 8; u++) {
                float4 kk = kr[u];
                s += q[u*4+0]*kk.x + q[u*4+1]*kk.y + q[u*4+2]*kk.z + q[u*4+3]*kk.w;
            }
            float e = __expf(s);
            l += e;
            const float4* vr = (const float4*)&vs[j][0];
            #pragma unroll
            for (int u = 0; u < 8; u++) {
                float4 vv = vr[u];
                acc[u*4+0] += e * vv.x;
                acc[u*4+1] += e * vv.y;
                acc[u*4+2] += e * vv.z;
                acc[u*4+3] += e * vv.w;
            }
        }
        __syncthreads();
    }

    const float inv = 1.0f / l;
    float* ob = g_oimg + ((size_t)(b * HID_) + h * DH_) * N_ + i;
    #pragma unroll
    for (int d = 0; d < DH_; d++)
        ob[(size_t)d * N_] = acc[d] * inv;
}

// ---------------------------------------------------------------------------
extern "C" void kernel_launch(void* const* d_in, const int* in_sizes, int n_in,
                              void* d_out, int out_size)
{
    (void)in_sizes; (void)n_in; (void)out_size;
    const float* x     = (const float*)d_in[0];
    const float* w_qkv = (const float*)d_in[1];
    const float* w_out = (const float*)d_in[2];
    const float* b_out = (const float*)d_in[3];
    float* y = (float*)d_out;

    float *qkv_p, *oimg_p;
    cudaGetSymbolAddress((void**)&qkv_p,  g_qkv);
    cudaGetSymbolAddress((void**)&oimg_p, g_oimg);

    // 1) QKV projection: [384x256] @ [256x4096] per batch
    gemm_wx<<<dim3(N_/64, OQKV_/64, B_), 256>>>(w_qkv, x, nullptr, qkv_p,
                                                OQKV_, CIN_, N_);
    // 2) per-row norms -> folded scale c[d]
    norm_kernel<<<B_ * HID_, 256>>>();
    // 3) attention
    attn_kernel<<<dim3(N_/128, B_ * HEADS_), 128>>>();
    // 4) output projection + bias: [256x128] @ [128x4096] per batch
    gemm_wx<<<dim3(N_/64, CIN_/64, B_), 256>>>(w_out, oimg_p, b_out, y,
                                               CIN_, HID_, N_);
}

// round 3
// speedup vs baseline: 4.8454x; 4.8454x over previous
#include <cuda_runtime.h>
#include <cuda_bf16.h>
#include <math.h>
#include <cstdint>

#define B_     4
#define CIN_   256
#define N_     4096
#define HEADS_ 4
#define DH_    32
#define HID_   128
#define OQKV_  384

// Scratch (allocation-free rule: __device__ globals)
__device__ float g_qkv[B_ * OQKV_ * N_];    // [b][o][n]: q 0..127, k 128..255, v 256..383
__device__ float g_scale[B_ * HID_];        // 10 / (||q_d|| ||k_d||)
__device__ float g_vsum[B_ * HID_];         // sum_j v[d][j] per (b, h*32+d)
__device__ float g_oimg[B_ * HID_ * N_];    // attention out, channel-major

// ---------------------------------------------------------------------------
// helpers
// ---------------------------------------------------------------------------
__device__ __forceinline__ uint32_t smem_to_u32(const void* p) {
    uint32_t a;
    asm("{ .reg .u64 t; cvta.to.shared.u64 t, %1; cvt.u32.u64 %0, t; }" : "=r"(a) : "l"(p));
    return a;
}

__device__ __forceinline__ void mma_bf16(float c[4],
                                         uint32_t a0, uint32_t a1, uint32_t a2, uint32_t a3,
                                         uint32_t b0, uint32_t b1) {
    asm volatile(
        "mma.sync.aligned.m16n8k16.row.col.f32.bf16.bf16.f32 "
        "{%0,%1,%2,%3}, {%4,%5,%6,%7}, {%8,%9}, {%0,%1,%2,%3};"
        : "+f"(c[0]), "+f"(c[1]), "+f"(c[2]), "+f"(c[3])
        : "r"(a0), "r"(a1), "r"(a2), "r"(a3), "r"(b0), "r"(b1));
}

__device__ __forceinline__ void ldsm4(uint32_t& r0, uint32_t& r1, uint32_t& r2, uint32_t& r3,
                                      uint32_t addr) {
    asm volatile("ldmatrix.sync.aligned.m8n8.x4.shared.b16 {%0,%1,%2,%3}, [%4];"
                 : "=r"(r0), "=r"(r1), "=r"(r2), "=r"(r3) : "r"(addr));
}
__device__ __forceinline__ void ldsm4t(uint32_t& r0, uint32_t& r1, uint32_t& r2, uint32_t& r3,
                                       uint32_t addr) {
    asm volatile("ldmatrix.sync.aligned.m8n8.x4.trans.shared.b16 {%0,%1,%2,%3}, [%4];"
                 : "=r"(r0), "=r"(r1), "=r"(r2), "=r"(r3) : "r"(addr));
}

__device__ __forceinline__ uint32_t packbf2(float lo, float hi) {
    __nv_bfloat162 p = __floats2bfloat162_rn(lo, hi);
    return *reinterpret_cast<uint32_t*>(&p);
}

// expm1(s) for |s| <~ 0.3: s*(1 + s*(1/2 + s*(1/6 + s/24))); abs err < 2e-5
__device__ __forceinline__ float expm1p(float s) {
    float t = fmaf(s, 0.041666668f, 0.16666667f);
    t = fmaf(s, t, 0.5f);
    t = fmaf(s, t, 1.0f);
    return s * t;
}

// tile layout: [j][d] bf16, row pitch 80B (4x16B data chunks + 16B pad),
// chunk c of row j stored at chunk (c ^ ((j>>3)&3)) -> conflict-free STS + LDSM
#define TPITCH 80u
#define SWZC(j, c) (((uint32_t)(c)) ^ ((((uint32_t)(j)) >> 3) & 3u))

// ---------------------------------------------------------------------------
// Batched GEMM: out[b][m][n] = sum_k W[m][k] * X[b][k][n] (+ bias[m])
// ---------------------------------------------------------------------------
__global__ void __launch_bounds__(256) gemm_wx(
    const float* __restrict__ W, const float* __restrict__ X,
    const float* __restrict__ bias, float* __restrict__ out,
    int M, int K, int N)
{
    __shared__ float As[16][68];
    __shared__ float Bs[16][68];

    const int b  = blockIdx.z;
    const int m0 = blockIdx.y * 64;
    const int n0 = blockIdx.x * 64;
    const int tid = threadIdx.x;
    const int ty = tid >> 4, tx = tid & 15;

    const float* Xb = X + (size_t)b * K * N;
    float acc[4][4] = {};

    for (int k0 = 0; k0 < K; k0 += 16) {
        #pragma unroll
        for (int t = tid; t < 64 * 16; t += 256) {
            int m = t >> 4, k = t & 15;
            As[k][m] = W[(size_t)(m0 + m) * K + k0 + k];
        }
        #pragma unroll
        for (int t = tid; t < 16 * 64; t += 256) {
            int k = t >> 6, n = t & 63;
            Bs[k][n] = Xb[(size_t)(k0 + k) * N + n0 + n];
        }
        __syncthreads();
        #pragma unroll
        for (int k = 0; k < 16; k++) {
            float4 a4 = *(const float4*)&As[k][ty * 4];
            float4 b4 = *(const float4*)&Bs[k][tx * 4];
            float av[4] = {a4.x, a4.y, a4.z, a4.w};
            float bv[4] = {b4.x, b4.y, b4.z, b4.w};
            #pragma unroll
            for (int i = 0; i < 4; i++)
                #pragma unroll
                for (int j = 0; j < 4; j++)
                    acc[i][j] += av[i] * bv[j];
        }
        __syncthreads();
    }

    #pragma unroll
    for (int i = 0; i < 4; i++) {
        int m = m0 + ty * 4 + i;
        float bv = bias ? bias[m] : 0.0f;
        float4 o4;
        o4.x = acc[i][0] + bv; o4.y = acc[i][1] + bv;
        o4.z = acc[i][2] + bv; o4.w = acc[i][3] + bv;
        *(float4*)(out + ((size_t)b * M + m) * N + n0 + tx * 4) = o4;
    }
}

// ---------------------------------------------------------------------------
// Per (b,hd): q,k row norms (-> folded scale) and v row sum.
// ---------------------------------------------------------------------------
__global__ void __launch_bounds__(256) norm_kernel()
{
    const int idx = blockIdx.x;
    const int b  = idx >> 7;
    const int hd = idx & 127;
    const float* q = g_qkv + ((size_t)(b * OQKV_ + hd)) * N_;
    const float* k = q + (size_t)HID_ * N_;
    const float* v = q + (size_t)(2 * HID_) * N_;

    float sq = 0.f, sk = 0.f, sv = 0.f;
    for (int i = threadIdx.x; i < N_; i += 256) {
        float a = q[i]; sq += a * a;
        float c = k[i]; sk += c * c;
        sv += v[i];
    }
    __shared__ float rq[256], rk[256], rv[256];
    rq[threadIdx.x] = sq; rk[threadIdx.x] = sk; rv[threadIdx.x] = sv;
    __syncthreads();
    for (int s = 128; s > 0; s >>= 1) {
        if (threadIdx.x < s) {
            rq[threadIdx.x] += rq[threadIdx.x + s];
            rk[threadIdx.x] += rk[threadIdx.x + s];
            rv[threadIdx.x] += rv[threadIdx.x + s];
        }
        __syncthreads();
    }
    if (threadIdx.x == 0) {
        float nq = fmaxf(sqrtf(rq[0]), 1e-12f);
        float nk = fmaxf(sqrtf(rk[0]), 1e-12f);
        g_scale[idx] = 10.0f / (nq * nk);
        g_vsum[idx]  = rv[0];
    }
}

// ---------------------------------------------------------------------------
// bf16 mma.sync flash attention with expm1 decomposition.
// grid = (32 i-tiles, 16 bh), 256 threads = 8 warps; warp owns 16 query rows.
// Per 64-wide j-tile:
//   S (16x64) = Q(16x32 bf16) . K'^T      [K' = k * folded scale, bf16]
//   delta = expm1(S); lsum += delta; P_A-frags = bf16(delta) (C-layout == A-layout)
//   OUT (16x32) += delta . V (bf16)
// Final: out = (vsum + OUT) / (4096 + lsum)   [exactly softmax(S) @ V]
// ---------------------------------------------------------------------------
__global__ void __launch_bounds__(256, 2) attn_mma_kernel()
{
    __shared__ __align__(16) unsigned char sbuf[2][10240];  // K(5120) + V(5120)
    __shared__ float cs[DH_];

    const int tid  = threadIdx.x;
    const int lane = tid & 31;
    const int w    = tid >> 5;
    const int g    = lane >> 2;
    const int tg   = lane & 3;

    const int bh = blockIdx.y;
    const int b = bh >> 2, h = bh & 3;
    const int i0 = blockIdx.x * 128 + w * 16;

    const float* qb = g_qkv + ((size_t)(b * OQKV_) + h * DH_) * N_;
    const float* kb = qb + (size_t)HID_ * N_;
    const float* vb = qb + (size_t)(2 * HID_) * N_;

    if (tid < DH_) cs[tid] = g_scale[bh * DH_ + tid];
    __syncthreads();

    // ---- Q fragments (2 k-steps of 16), loaded once -------------------------
    uint32_t qa[2][4];
    #pragma unroll
    for (int ks = 0; ks < 2; ks++) {
        #pragma unroll
        for (int rr = 0; rr < 4; rr++) {
            int r = i0 + g + ((rr & 1) ? 8 : 0);
            int d = ks * 16 + 2 * tg + ((rr >> 1) ? 8 : 0);
            float f0 = qb[(size_t)d * N_ + r];
            float f1 = qb[(size_t)(d + 1) * N_ + r];
            qa[ks][rr] = packbf2(f0, f1);
        }
    }

    // ---- tile stage: each thread loads 4 (j, d-pair) words of K and V -------
    const int jj  = tid & 63;
    const int dp0 = tid >> 6;      // 0..3; dp = dp0 + 4t

    float kf[8], vf[8];
    auto load_regs = [&](int jt) {
        #pragma unroll
        for (int t = 0; t < 4; t++) {
            int dp = dp0 + 4 * t;
            kf[2*t]   = kb[(size_t)(2*dp)   * N_ + jt + jj];
            kf[2*t+1] = kb[(size_t)(2*dp+1) * N_ + jt + jj];
            vf[2*t]   = vb[(size_t)(2*dp)   * N_ + jt + jj];
            vf[2*t+1] = vb[(size_t)(2*dp+1) * N_ + jt + jj];
        }
    };
    auto store_tile = [&](unsigned char* buf) {
        #pragma unroll
        for (int t = 0; t < 4; t++) {
            int dp = dp0 + 4 * t;
            uint32_t off = (uint32_t)jj * TPITCH + SWZC(jj, dp >> 2) * 16u + (dp & 3) * 4u;
            *(uint32_t*)(buf + off)        = packbf2(kf[2*t] * cs[2*dp], kf[2*t+1] * cs[2*dp+1]);
            *(uint32_t*)(buf + 5120 + off) = packbf2(vf[2*t], vf[2*t+1]);
        }
    };

    float oacc[4][4] = {};
    float lsumA = 0.0f, lsumB = 0.0f;

    load_regs(0);
    store_tile(sbuf[0]);
    __syncthreads();

    for (int ti = 0; ti < 64; ti++) {
        if (ti < 63) load_regs((ti + 1) * 64);

        const uint32_t smK = smem_to_u32(sbuf[ti & 1]);
        const uint32_t smV = smK + 5120;

        // S = Q . K'^T : 8 n-blocks of 8 j, 2 k-steps
        float sc[8][4];
        #pragma unroll
        for (int nb = 0; nb < 8; nb++) {
            sc[nb][0] = sc[nb][1] = sc[nb][2] = sc[nb][3] = 0.0f;
            uint32_t r0, r1, r2, r3;
            uint32_t jrow = (uint32_t)(nb * 8 + (lane & 7));
            uint32_t addr = smK + jrow * TPITCH + SWZC(jrow, lane >> 3) * 16u;
            ldsm4(r0, r1, r2, r3, addr);
            mma_bf16(sc[nb], qa[0][0], qa[0][1], qa[0][2], qa[0][3], r0, r1);
            mma_bf16(sc[nb], qa[1][0], qa[1][1], qa[1][2], qa[1][3], r2, r3);
        }

        // epilogue: delta = expm1(s); accumulate lsum; build P A-fragments
        uint32_t pa[4][4];
        #pragma unroll
        for (int nb = 0; nb < 8; nb++) {
            float d0 = expm1p(sc[nb][0]);
            float d1 = expm1p(sc[nb][1]);
            float d2 = expm1p(sc[nb][2]);
            float d3 = expm1p(sc[nb][3]);
            lsumA += d0 + d1;
            lsumB += d2 + d3;
            pa[nb >> 1][(nb & 1) * 2 + 0] = packbf2(d0, d1);
            pa[nb >> 1][(nb & 1) * 2 + 1] = packbf2(d2, d3);
        }

        // OUT += delta . V : 4 d-blocks x 4 j-k-steps
        #pragma unroll
        for (int nbd = 0; nbd < 4; nbd++) {
            uint32_t v0, v1, v2, v3, v4, v5, v6, v7;
            uint32_t j1 = (uint32_t)lane;
            uint32_t j2 = (uint32_t)(32 + lane);
            ldsm4t(v0, v1, v2, v3, smV + j1 * TPITCH + SWZC(j1, nbd) * 16u);
            ldsm4t(v4, v5, v6, v7, smV + j2 * TPITCH + SWZC(j2, nbd) * 16u);
            mma_bf16(oacc[nbd], pa[0][0], pa[0][1], pa[0][2], pa[0][3], v0, v1);
            mma_bf16(oacc[nbd], pa[1][0], pa[1][1], pa[1][2], pa[1][3], v2, v3);
            mma_bf16(oacc[nbd], pa[2][0], pa[2][1], pa[2][2], pa[2][3], v4, v5);
            mma_bf16(oacc[nbd], pa[3][0], pa[3][1], pa[3][2], pa[3][3], v6, v7);
        }

        if (ti < 63) {
            store_tile(sbuf[(ti + 1) & 1]);
            __syncthreads();
        }
    }

    // reduce lsum across the 4 lanes of each row group
    lsumA += __shfl_xor_sync(0xffffffffu, lsumA, 1);
    lsumA += __shfl_xor_sync(0xffffffffu, lsumA, 2);
    lsumB += __shfl_xor_sync(0xffffffffu, lsumB, 1);
    lsumB += __shfl_xor_sync(0xffffffffu, lsumB, 2);
    const float rA = 1.0f / (4096.0f + lsumA);
    const float rB = 1.0f / (4096.0f + lsumB);

    // out = (vsum + OUT) / denom, written channel-major
    const int chan0 = b * HID_ + h * DH_;
    const int iA = i0 + g, iB = i0 + g + 8;
    #pragma unroll
    for (int nbd = 0; nbd < 4; nbd++) {
        int d0 = nbd * 8 + 2 * tg;
        float vs0 = g_vsum[chan0 + d0];
        float vs1 = g_vsum[chan0 + d0 + 1];
        g_oimg[(size_t)(chan0 + d0)     * N_ + iA] = (vs0 + oacc[nbd][0]) * rA;
        g_oimg[(size_t)(chan0 + d0 + 1) * N_ + iA] = (vs1 + oacc[nbd][1]) * rA;
        g_oimg[(size_t)(chan0 + d0)     * N_ + iB] = (vs0 + oacc[nbd][2]) * rB;
        g_oimg[(size_t)(chan0 + d0 + 1) * N_ + iB] = (vs1 + oacc[nbd][3]) * rB;
    }
}

// ---------------------------------------------------------------------------
extern "C" void kernel_launch(void* const* d_in, const int* in_sizes, int n_in,
                              void* d_out, int out_size)
{
    (void)in_sizes; (void)n_in; (void)out_size;
    const float* x     = (const float*)d_in[0];
    const float* w_qkv = (const float*)d_in[1];
    const float* w_out = (const float*)d_in[2];
    const float* b_out = (const float*)d_in[3];
    float* y = (float*)d_out;

    float *qkv_p, *oimg_p;
    cudaGetSymbolAddress((void**)&qkv_p,  g_qkv);
    cudaGetSymbolAddress((void**)&oimg_p, g_oimg);

    gemm_wx<<<dim3(N_/64, OQKV_/64, B_), 256>>>(w_qkv, x, nullptr, qkv_p,
                                                OQKV_, CIN_, N_);
    norm_kernel<<<B_ * HID_, 256>>>();
    attn_mma_kernel<<<dim3(N_/128, B_ * HEADS_), 256>>>();
    gemm_wx<<<dim3(N_/64, CIN_/64, B_), 256>>>(w_out, oimg_p, b_out, y,
                                               CIN_, HID_, N_);
}

// round 4
// speedup vs baseline: 5.5255x; 1.1404x over previous
#include <cuda_runtime.h>
#include <cuda_bf16.h>
#include <math.h>
#include <cstdint>

#define B_     4
#define CIN_   256
#define N_     4096
#define HEADS_ 4
#define DH_    32
#define HID_   128
#define OQKV_  384
#define TPITCH 80u
#define TILEB  10240

// Scratch (allocation-free rule: __device__ globals)
__device__ float g_qkv[B_ * OQKV_ * N_];    // [b][o][n]: q 0..127, k 128..255, v 256..383
__device__ float g_scale[B_ * HID_];        // 10 / (||q_d|| ||k_d||)
__device__ float g_vsum[B_ * HID_];         // sum_j v[d][j]
__device__ float g_oimg[B_ * HID_ * N_];    // attention out, channel-major
// packed bf16 tiles, byte-identical to attention smem stage layout:
// [bh][tile ti][ K: 64 rows x (4x16B data + 16B zero-pad) | V: same, pad=(1,0..) ]
__device__ __align__(16) unsigned char g_pack[16 * 64 * TILEB];

// ---------------------------------------------------------------------------
// helpers
// ---------------------------------------------------------------------------
__device__ __forceinline__ uint32_t smem_to_u32(const void* p) {
    uint32_t a;
    asm("{ .reg .u64 t; cvta.to.shared.u64 t, %1; cvt.u32.u64 %0, t; }" : "=r"(a) : "l"(p));
    return a;
}

__device__ __forceinline__ void mma_bf16(float c[4],
                                         uint32_t a0, uint32_t a1, uint32_t a2, uint32_t a3,
                                         uint32_t b0, uint32_t b1) {
    asm volatile(
        "mma.sync.aligned.m16n8k16.row.col.f32.bf16.bf16.f32 "
        "{%0,%1,%2,%3}, {%4,%5,%6,%7}, {%8,%9}, {%0,%1,%2,%3};"
        : "+f"(c[0]), "+f"(c[1]), "+f"(c[2]), "+f"(c[3])
        : "r"(a0), "r"(a1), "r"(a2), "r"(a3), "r"(b0), "r"(b1));
}

__device__ __forceinline__ void ldsm4(uint32_t& r0, uint32_t& r1, uint32_t& r2, uint32_t& r3,
                                      uint32_t addr) {
    asm volatile("ldmatrix.sync.aligned.m8n8.x4.shared.b16 {%0,%1,%2,%3}, [%4];"
                 : "=r"(r0), "=r"(r1), "=r"(r2), "=r"(r3) : "r"(addr));
}
__device__ __forceinline__ void ldsm4t(uint32_t& r0, uint32_t& r1, uint32_t& r2, uint32_t& r3,
                                       uint32_t addr) {
    asm volatile("ldmatrix.sync.aligned.m8n8.x4.trans.shared.b16 {%0,%1,%2,%3}, [%4];"
                 : "=r"(r0), "=r"(r1), "=r"(r2), "=r"(r3) : "r"(addr));
}

__device__ __forceinline__ uint32_t packbf2(float lo, float hi) {
    __nv_bfloat162 p = __floats2bfloat162_rn(lo, hi);
    return *reinterpret_cast<uint32_t*>(&p);
}

__device__ __forceinline__ void cp_async16(uint32_t s, const void* g) {
    asm volatile("cp.async.cg.shared.global [%0], [%1], 16;" :: "r"(s), "l"(g));
}

// expm1(s) for |s| <~ 0.15: s*(1 + s*(1/2 + s/6)); abs err < 4e-6
__device__ __forceinline__ float expm1p(float s) {
    float t = fmaf(s, 0.16666667f, 0.5f);
    t = fmaf(s, t, 1.0f);
    return s * t;
}

// ---------------------------------------------------------------------------
// Batched GEMM: out[b][m][n] = sum_k W[m][k] * X[b][k][n] (+ bias[m])
// 128x128 tile, K-step 16, 256 threads, 8x8 microtile (4+4 split rows/cols).
// ---------------------------------------------------------------------------
__global__ void __launch_bounds__(256) gemm_wx(
    const float* __restrict__ W, const float* __restrict__ X,
    const float* __restrict__ bias, float* __restrict__ out,
    int M, int K, int N)
{
    __shared__ float As[16][132];   // [k][m]
    __shared__ float Bs[16][132];   // [k][n]

    const int b  = blockIdx.z;
    const int m0 = blockIdx.y * 128;
    const int n0 = blockIdx.x * 128;
    const int tid = threadIdx.x;
    const int ty = tid >> 4, tx = tid & 15;

    const float* Xb = X + (size_t)b * K * N;
    float acc[8][8] = {};

    for (int k0 = 0; k0 < K; k0 += 16) {
        #pragma unroll
        for (int s = 0; s < 2; s++) {
            int t = tid * 2 + s;
            int m = t >> 2, kq = t & 3;
            float4 f = *(const float4*)&W[(size_t)(m0 + m) * K + k0 + kq * 4];
            As[kq * 4 + 0][m] = f.x; As[kq * 4 + 1][m] = f.y;
            As[kq * 4 + 2][m] = f.z; As[kq * 4 + 3][m] = f.w;
        }
        #pragma unroll
        for (int s = 0; s < 2; s++) {
            int t = tid * 2 + s;
            int k = t >> 5, nq = t & 31;
            *(float4*)&Bs[k][nq * 4] = *(const float4*)&Xb[(size_t)(k0 + k) * N + n0 + nq * 4];
        }
        __syncthreads();
        #pragma unroll
        for (int k = 0; k < 16; k++) {
            float4 a0 = *(const float4*)&As[k][ty * 4];
            float4 a1 = *(const float4*)&As[k][64 + ty * 4];
            float4 b0 = *(const float4*)&Bs[k][tx * 4];
            float4 b1 = *(const float4*)&Bs[k][64 + tx * 4];
            float av[8] = {a0.x, a0.y, a0.z, a0.w, a1.x, a1.y, a1.z, a1.w};
            float bv[8] = {b0.x, b0.y, b0.z, b0.w, b1.x, b1.y, b1.z, b1.w};
            #pragma unroll
            for (int i = 0; i < 8; i++)
                #pragma unroll
                for (int j = 0; j < 8; j++)
                    acc[i][j] += av[i] * bv[j];
        }
        __syncthreads();
    }

    #pragma unroll
    for (int i = 0; i < 8; i++) {
        int m = m0 + ((i < 4) ? (ty * 4 + i) : (64 + ty * 4 + i - 4));
        float bv = bias ? bias[m] : 0.0f;
        float4 o0, o1;
        o0.x = acc[i][0] + bv; o0.y = acc[i][1] + bv;
        o0.z = acc[i][2] + bv; o0.w = acc[i][3] + bv;
        o1.x = acc[i][4] + bv; o1.y = acc[i][5] + bv;
        o1.z = acc[i][6] + bv; o1.w = acc[i][7] + bv;
        *(float4*)(out + ((size_t)b * M + m) * N + n0 + tx * 4) = o0;
        *(float4*)(out + ((size_t)b * M + m) * N + n0 + 64 + tx * 4) = o1;
    }
}

// ---------------------------------------------------------------------------
// Per (b,hd): q,k row norms (-> folded scale) and v row sum.
// ---------------------------------------------------------------------------
__global__ void __launch_bounds__(256) norm_kernel()
{
    const int idx = blockIdx.x;
    const int b  = idx >> 7;
    const int hd = idx & 127;
    const float* q = g_qkv + ((size_t)(b * OQKV_ + hd)) * N_;
    const float* k = q + (size_t)HID_ * N_;
    const float* v = q + (size_t)(2 * HID_) * N_;

    float sq = 0.f, sk = 0.f, sv = 0.f;
    for (int i = threadIdx.x; i < N_; i += 256) {
        float a = q[i]; sq += a * a;
        float c = k[i]; sk += c * c;
        sv += v[i];
    }
    __shared__ float rq[256], rk[256], rv[256];
    rq[threadIdx.x] = sq; rk[threadIdx.x] = sk; rv[threadIdx.x] = sv;
    __syncthreads();
    for (int s = 128; s > 0; s >>= 1) {
        if (threadIdx.x < s) {
            rq[threadIdx.x] += rq[threadIdx.x + s];
            rk[threadIdx.x] += rk[threadIdx.x + s];
            rv[threadIdx.x] += rv[threadIdx.x + s];
        }
        __syncthreads();
    }
    if (threadIdx.x == 0) {
        float nq = fmaxf(sqrtf(rq[0]), 1e-12f);
        float nk = fmaxf(sqrtf(rk[0]), 1e-12f);
        g_scale[idx] = 10.0f / (nq * nk);
        g_vsum[idx]  = rv[0];
    }
}

// ---------------------------------------------------------------------------
// Pack K' (k * folded scale) and V into bf16 LDSM-ready tiles.
// grid (64 tiles, 16 bh), 256 threads: thread = (j in 0..63, dgroup 0..3),
// builds one 16B chunk of K and one of V. Pad chunk: K zeros, V (1,0,...).
// ---------------------------------------------------------------------------
__global__ void __launch_bounds__(256) pack_kernel()
{
    const int bh = blockIdx.y, ti = blockIdx.x;
    const int b = bh >> 2, h = bh & 3;
    const float* kb = g_qkv + ((size_t)(b * OQKV_) + HID_ + h * DH_) * N_;
    const float* vb = kb + (size_t)HID_ * N_;

    const int j  = threadIdx.x & 63;
    const int dg = threadIdx.x >> 6;
    const int jt = ti * 64;
    unsigned char* out = g_pack + ((size_t)bh * 64 + ti) * TILEB;

    uint32_t kw[4], vw[4];
    #pragma unroll
    for (int p = 0; p < 4; p++) {
        int d = dg * 8 + 2 * p;
        float c0 = g_scale[bh * DH_ + d];
        float c1 = g_scale[bh * DH_ + d + 1];
        float k0 = kb[(size_t)d * N_ + jt + j];
        float k1 = kb[(size_t)(d + 1) * N_ + jt + j];
        kw[p] = packbf2(k0 * c0, k1 * c1);
        vw[p] = packbf2(vb[(size_t)d * N_ + jt + j], vb[(size_t)(d + 1) * N_ + jt + j]);
    }
    *(uint4*)(out + j * TPITCH + dg * 16)        = make_uint4(kw[0], kw[1], kw[2], kw[3]);
    *(uint4*)(out + 5120 + j * TPITCH + dg * 16) = make_uint4(vw[0], vw[1], vw[2], vw[3]);

    if (threadIdx.x < 64) {
        *(uint4*)(out + threadIdx.x * TPITCH + 64) = make_uint4(0u, 0u, 0u, 0u);
    } else if (threadIdx.x < 128) {
        int jj = threadIdx.x - 64;  // V pad: d=32 column of ones (lsum via MMA)
        *(uint4*)(out + 5120 + jj * TPITCH + 64) = make_uint4(0x00003F80u, 0u, 0u, 0u);
    }
}

// ---------------------------------------------------------------------------
// bf16 mma.sync flash attention, cp.async 4-stage pipeline, lsum via ones-col.
// grid = (32 i-tiles, 16 bh), 256 threads = 8 warps; warp owns 16 query rows.
//   S (16x64) = Q . K'^T;  delta = expm1(S) -> bf16 A-frags (C-layout==A-layout)
//   OUT(16x40) += delta . [V | ones]  -> col 32 accumulates lsum
//   out = (vsum + OUT) / (4096 + lsum)
// ---------------------------------------------------------------------------
__global__ void __launch_bounds__(256, 2) attn_mma_kernel()
{
    __shared__ __align__(16) unsigned char sbuf[4][TILEB];  // 40 KB

    const int tid  = threadIdx.x;
    const int lane = tid & 31;
    const int w    = tid >> 5;
    const int g    = lane >> 2;
    const int tg   = lane & 3;

    const int bh = blockIdx.y;
    const int b = bh >> 2, h = bh & 3;
    const int i0 = blockIdx.x * 128 + w * 16;

    const float* qb = g_qkv + ((size_t)(b * OQKV_) + h * DH_) * N_;
    const unsigned char* pk = g_pack + (size_t)bh * 64 * TILEB;

    // Q fragments (2 k-steps of 16), loaded once
    uint32_t qa[2][4];
    #pragma unroll
    for (int ks = 0; ks < 2; ks++) {
        #pragma unroll
        for (int rr = 0; rr < 4; rr++) {
            int r = i0 + g + ((rr & 1) ? 8 : 0);
            int d = ks * 16 + 2 * tg + ((rr >> 1) ? 8 : 0);
            qa[ks][rr] = packbf2(qb[(size_t)d * N_ + r], qb[(size_t)(d + 1) * N_ + r]);
        }
    }

    auto issue = [&](int ti) {
        const unsigned char* src = pk + (size_t)ti * TILEB;
        uint32_t dst = smem_to_u32(sbuf[ti & 3]);
        cp_async16(dst + tid * 16, src + tid * 16);
        cp_async16(dst + (tid + 256) * 16, src + (tid + 256) * 16);
        if (tid < 128) cp_async16(dst + (tid + 512) * 16, src + (tid + 512) * 16);
        asm volatile("cp.async.commit_group;" ::: "memory");
    };

    float oacc[5][4] = {};

    issue(0); issue(1); issue(2);

    for (int ti = 0; ti < 64; ti++) {
        asm volatile("cp.async.wait_group 2;" ::: "memory");
        __syncthreads();
        if (ti + 3 < 64) issue(ti + 3);   // into buf consumed at ti-1, safe post-sync

        const uint32_t smK = smem_to_u32(sbuf[ti & 3]);
        const uint32_t smV = smK + 5120;

        // S = Q . K'^T : 8 n-blocks of 8 j, 2 k-steps
        float sc[8][4];
        #pragma unroll
        for (int nb = 0; nb < 8; nb++) {
            sc[nb][0] = sc[nb][1] = sc[nb][2] = sc[nb][3] = 0.0f;
            uint32_t r0, r1, r2, r3;
            uint32_t jrow = (uint32_t)(nb * 8 + (lane & 7));
            ldsm4(r0, r1, r2, r3, smK + jrow * TPITCH + (uint32_t)(lane >> 3) * 16u);
            mma_bf16(sc[nb], qa[0][0], qa[0][1], qa[0][2], qa[0][3], r0, r1);
            mma_bf16(sc[nb], qa[1][0], qa[1][1], qa[1][2], qa[1][3], r2, r3);
        }

        // delta = expm1(s) -> bf16 A-fragments (lsum handled by ones column)
        uint32_t pa[4][4];
        #pragma unroll
        for (int nb = 0; nb < 8; nb++) {
            float d0 = expm1p(sc[nb][0]);
            float d1 = expm1p(sc[nb][1]);
            float d2 = expm1p(sc[nb][2]);
            float d3 = expm1p(sc[nb][3]);
            pa[nb >> 1][(nb & 1) * 2 + 0] = packbf2(d0, d1);
            pa[nb >> 1][(nb & 1) * 2 + 1] = packbf2(d2, d3);
        }

        // OUT += delta . [V | ones] : 5 d-blocks x 4 j-k-steps
        #pragma unroll
        for (int nbd = 0; nbd < 5; nbd++) {
            uint32_t v0, v1, v2, v3, v4, v5, v6, v7;
            ldsm4t(v0, v1, v2, v3, smV + (uint32_t)lane * TPITCH + (uint32_t)nbd * 16u);
            ldsm4t(v4, v5, v6, v7, smV + (uint32_t)(32 + lane) * TPITCH + (uint32_t)nbd * 16u);
            mma_bf16(oacc[nbd], pa[0][0], pa[0][1], pa[0][2], pa[0][3], v0, v1);
            mma_bf16(oacc[nbd], pa[1][0], pa[1][1], pa[1][2], pa[1][3], v2, v3);
            mma_bf16(oacc[nbd], pa[2][0], pa[2][1], pa[2][2], pa[2][3], v4, v5);
            mma_bf16(oacc[nbd], pa[3][0], pa[3][1], pa[3][2], pa[3][3], v6, v7);
        }
    }

    // lsum lives in OUT col 32 (block 4, col 0) owned by tg=0 lanes
    float lA = __shfl_sync(0xffffffffu, oacc[4][0], lane & ~3);
    float lB = __shfl_sync(0xffffffffu, oacc[4][2], lane & ~3);
    const float rA = 1.0f / (4096.0f + lA);
    const float rB = 1.0f / (4096.0f + lB);

    // out = (vsum + OUT) / denom, channel-major
    const int chan0 = b * HID_ + h * DH_;
    const int iA = i0 + g, iB = i0 + g + 8;
    #pragma unroll
    for (int nbd = 0; nbd < 4; nbd++) {
        int d0 = nbd * 8 + 2 * tg;
        float vs0 = g_vsum[chan0 + d0];
        float vs1 = g_vsum[chan0 + d0 + 1];
        g_oimg[(size_t)(chan0 + d0)     * N_ + iA] = (vs0 + oacc[nbd][0]) * rA;
        g_oimg[(size_t)(chan0 + d0 + 1) * N_ + iA] = (vs1 + oacc[nbd][1]) * rA;
        g_oimg[(size_t)(chan0 + d0)     * N_ + iB] = (vs0 + oacc[nbd][2]) * rB;
        g_oimg[(size_t)(chan0 + d0 + 1) * N_ + iB] = (vs1 + oacc[nbd][3]) * rB;
    }
}

// ---------------------------------------------------------------------------
extern "C" void kernel_launch(void* const* d_in, const int* in_sizes, int n_in,
                              void* d_out, int out_size)
{
    (void)in_sizes; (void)n_in; (void)out_size;
    const float* x     = (const float*)d_in[0];
    const float* w_qkv = (const float*)d_in[1];
    const float* w_out = (const float*)d_in[2];
    const float* b_out = (const float*)d_in[3];
    float* y = (float*)d_out;

    float *qkv_p, *oimg_p;
    cudaGetSymbolAddress((void**)&qkv_p,  g_qkv);
    cudaGetSymbolAddress((void**)&oimg_p, g_oimg);

    gemm_wx<<<dim3(N_/128, OQKV_/128, B_), 256>>>(w_qkv, x, nullptr, qkv_p,
                                                  OQKV_, CIN_, N_);
    norm_kernel<<<B_ * HID_, 256>>>();
    pack_kernel<<<dim3(64, 16), 256>>>();
    attn_mma_kernel<<<dim3(N_/128, B_ * HEADS_), 256>>>();
    gemm_wx<<<dim3(N_/128, CIN_/128, B_), 256>>>(w_out, oimg_p, b_out, y,
                                                 CIN_, HID_, N_);
}

// round 5
// speedup vs baseline: 5.8079x; 1.0511x over previous
#include <cuda_runtime.h>
#include <cuda_bf16.h>
#include <math.h>
#include <cstdint>

#define B_     4
#define CIN_   256
#define N_     4096
#define HEADS_ 4
#define DH_    32
#define HID_   128
#define OQKV_  384
#define TPITCH 80u
#define TILEB  10240

// Scratch (allocation-free rule: __device__ globals)
__device__ float g_qkv[B_ * OQKV_ * N_];    // [b][o][n]: q 0..127, k 128..255, v 256..383
__device__ float g_scale[B_ * HID_];        // 10 / (||q_d|| ||k_d||)
__device__ float g_vsum[B_ * HID_];         // sum_j v[d][j]
__device__ float g_oimg[B_ * HID_ * N_];    // attention out, channel-major
// packed bf16 tiles, byte-identical to attention smem stage layout:
// [bh][tile ti][ K: 64 rows x (4x16B data + 16B zero-pad) | V: same, pad=(1,0..) ]
__device__ __align__(16) unsigned char g_pack[16 * 64 * TILEB];

// ---------------------------------------------------------------------------
// helpers
// ---------------------------------------------------------------------------
__device__ __forceinline__ uint32_t smem_to_u32(const void* p) {
    uint32_t a;
    asm("{ .reg .u64 t; cvta.to.shared.u64 t, %1; cvt.u32.u64 %0, t; }" : "=r"(a) : "l"(p));
    return a;
}

__device__ __forceinline__ void mma_bf16(float c[4],
                                         uint32_t a0, uint32_t a1, uint32_t a2, uint32_t a3,
                                         uint32_t b0, uint32_t b1) {
    asm volatile(
        "mma.sync.aligned.m16n8k16.row.col.f32.bf16.bf16.f32 "
        "{%0,%1,%2,%3}, {%4,%5,%6,%7}, {%8,%9}, {%0,%1,%2,%3};"
        : "+f"(c[0]), "+f"(c[1]), "+f"(c[2]), "+f"(c[3])
        : "r"(a0), "r"(a1), "r"(a2), "r"(a3), "r"(b0), "r"(b1));
}

__device__ __forceinline__ void ldsm4(uint32_t& r0, uint32_t& r1, uint32_t& r2, uint32_t& r3,
                                      uint32_t addr) {
    asm volatile("ldmatrix.sync.aligned.m8n8.x4.shared.b16 {%0,%1,%2,%3}, [%4];"
                 : "=r"(r0), "=r"(r1), "=r"(r2), "=r"(r3) : "r"(addr));
}
__device__ __forceinline__ void ldsm4t(uint32_t& r0, uint32_t& r1, uint32_t& r2, uint32_t& r3,
                                       uint32_t addr) {
    asm volatile("ldmatrix.sync.aligned.m8n8.x4.trans.shared.b16 {%0,%1,%2,%3}, [%4];"
                 : "=r"(r0), "=r"(r1), "=r"(r2), "=r"(r3) : "r"(addr));
}

__device__ __forceinline__ uint32_t packbf2(float lo, float hi) {
    __nv_bfloat162 p = __floats2bfloat162_rn(lo, hi);
    return *reinterpret_cast<uint32_t*>(&p);
}
__device__ __forceinline__ uint32_t bf2u(__nv_bfloat162 p) {
    return *reinterpret_cast<uint32_t*>(&p);
}

__device__ __forceinline__ void cp_async16(uint32_t s, const void* g) {
    asm volatile("cp.async.cg.shared.global [%0], [%1], 16;" :: "r"(s), "l"(g));
}

// ---------------------------------------------------------------------------
// Batched GEMM: out[b][m][n] = sum_k W[m][k] * X[b][k][n] (+ bias[m])
// 128x128 tile, K-step 16, 256 threads, 8x8 microtile (4+4 split rows/cols).
// ---------------------------------------------------------------------------
__global__ void __launch_bounds__(256) gemm_wx(
    const float* __restrict__ W, const float* __restrict__ X,
    const float* __restrict__ bias, float* __restrict__ out,
    int M, int K, int N)
{
    __shared__ float As[16][132];   // [k][m]
    __shared__ float Bs[16][132];   // [k][n]

    const int b  = blockIdx.z;
    const int m0 = blockIdx.y * 128;
    const int n0 = blockIdx.x * 128;
    const int tid = threadIdx.x;
    const int ty = tid >> 4, tx = tid & 15;

    const float* Xb = X + (size_t)b * K * N;
    float acc[8][8] = {};

    for (int k0 = 0; k0 < K; k0 += 16) {
        #pragma unroll
        for (int s = 0; s < 2; s++) {
            int t = tid * 2 + s;
            int m = t >> 2, kq = t & 3;
            float4 f = *(const float4*)&W[(size_t)(m0 + m) * K + k0 + kq * 4];
            As[kq * 4 + 0][m] = f.x; As[kq * 4 + 1][m] = f.y;
            As[kq * 4 + 2][m] = f.z; As[kq * 4 + 3][m] = f.w;
        }
        #pragma unroll
        for (int s = 0; s < 2; s++) {
            int t = tid * 2 + s;
            int k = t >> 5, nq = t & 31;
            *(float4*)&Bs[k][nq * 4] = *(const float4*)&Xb[(size_t)(k0 + k) * N + n0 + nq * 4];
        }
        __syncthreads();
        #pragma unroll
        for (int k = 0; k < 16; k++) {
            float4 a0 = *(const float4*)&As[k][ty * 4];
            float4 a1 = *(const float4*)&As[k][64 + ty * 4];
            float4 b0 = *(const float4*)&Bs[k][tx * 4];
            float4 b1 = *(const float4*)&Bs[k][64 + tx * 4];
            float av[8] = {a0.x, a0.y, a0.z, a0.w, a1.x, a1.y, a1.z, a1.w};
            float bv[8] = {b0.x, b0.y, b0.z, b0.w, b1.x, b1.y, b1.z, b1.w};
            #pragma unroll
            for (int i = 0; i < 8; i++)
                #pragma unroll
                for (int j = 0; j < 8; j++)
                    acc[i][j] += av[i] * bv[j];
        }
        __syncthreads();
    }

    #pragma unroll
    for (int i = 0; i < 8; i++) {
        int m = m0 + ((i < 4) ? (ty * 4 + i) : (64 + ty * 4 + i - 4));
        float bv = bias ? bias[m] : 0.0f;
        float4 o0, o1;
        o0.x = acc[i][0] + bv; o0.y = acc[i][1] + bv;
        o0.z = acc[i][2] + bv; o0.w = acc[i][3] + bv;
        o1.x = acc[i][4] + bv; o1.y = acc[i][5] + bv;
        o1.z = acc[i][6] + bv; o1.w = acc[i][7] + bv;
        *(float4*)(out + ((size_t)b * M + m) * N + n0 + tx * 4) = o0;
        *(float4*)(out + ((size_t)b * M + m) * N + n0 + 64 + tx * 4) = o1;
    }
}

// ---------------------------------------------------------------------------
// Per (b,hd): q,k row norms (-> folded scale) and v row sum.
// ---------------------------------------------------------------------------
__global__ void __launch_bounds__(256) norm_kernel()
{
    const int idx = blockIdx.x;
    const int b  = idx >> 7;
    const int hd = idx & 127;
    const float* q = g_qkv + ((size_t)(b * OQKV_ + hd)) * N_;
    const float* k = q + (size_t)HID_ * N_;
    const float* v = q + (size_t)(2 * HID_) * N_;

    float sq = 0.f, sk = 0.f, sv = 0.f;
    for (int i = threadIdx.x; i < N_; i += 256) {
        float a = q[i]; sq += a * a;
        float c = k[i]; sk += c * c;
        sv += v[i];
    }
    __shared__ float rq[256], rk[256], rv[256];
    rq[threadIdx.x] = sq; rk[threadIdx.x] = sk; rv[threadIdx.x] = sv;
    __syncthreads();
    for (int s = 128; s > 0; s >>= 1) {
        if (threadIdx.x < s) {
            rq[threadIdx.x] += rq[threadIdx.x + s];
            rk[threadIdx.x] += rk[threadIdx.x + s];
            rv[threadIdx.x] += rv[threadIdx.x + s];
        }
        __syncthreads();
    }
    if (threadIdx.x == 0) {
        float nq = fmaxf(sqrtf(rq[0]), 1e-12f);
        float nk = fmaxf(sqrtf(rk[0]), 1e-12f);
        g_scale[idx] = 10.0f / (nq * nk);
        g_vsum[idx]  = rv[0];
    }
}

// ---------------------------------------------------------------------------
// Pack K' (k * folded scale) and V into bf16 LDSM-ready tiles.
// ---------------------------------------------------------------------------
__global__ void __launch_bounds__(256) pack_kernel()
{
    const int bh = blockIdx.y, ti = blockIdx.x;
    const int b = bh >> 2, h = bh & 3;
    const float* kb = g_qkv + ((size_t)(b * OQKV_) + HID_ + h * DH_) * N_;
    const float* vb = kb + (size_t)HID_ * N_;

    const int j  = threadIdx.x & 63;
    const int dg = threadIdx.x >> 6;
    const int jt = ti * 64;
    unsigned char* out = g_pack + ((size_t)bh * 64 + ti) * TILEB;

    uint32_t kw[4], vw[4];
    #pragma unroll
    for (int p = 0; p < 4; p++) {
        int d = dg * 8 + 2 * p;
        float c0 = g_scale[bh * DH_ + d];
        float c1 = g_scale[bh * DH_ + d + 1];
        float k0 = kb[(size_t)d * N_ + jt + j];
        float k1 = kb[(size_t)(d + 1) * N_ + jt + j];
        kw[p] = packbf2(k0 * c0, k1 * c1);
        vw[p] = packbf2(vb[(size_t)d * N_ + jt + j], vb[(size_t)(d + 1) * N_ + jt + j]);
    }
    *(uint4*)(out + j * TPITCH + dg * 16)        = make_uint4(kw[0], kw[1], kw[2], kw[3]);
    *(uint4*)(out + 5120 + j * TPITCH + dg * 16) = make_uint4(vw[0], vw[1], vw[2], vw[3]);

    if (threadIdx.x < 64) {
        *(uint4*)(out + threadIdx.x * TPITCH + 64) = make_uint4(0u, 0u, 0u, 0u);
    } else if (threadIdx.x < 128) {
        int jj = threadIdx.x - 64;  // V pad: d=32 column of ones (lsum via MMA)
        *(uint4*)(out + 5120 + jj * TPITCH + 64) = make_uint4(0x00003F80u, 0u, 0u, 0u);
    }
}

// ---------------------------------------------------------------------------
// bf16 mma.sync flash attention, cp.async 4-stage pipeline, lsum via ones-col.
// grid = (32 i-tiles, 16 bh), 256 threads = 8 warps; warp owns 16 query rows.
// Tile processed in two halves of 4 n-blocks (reduces live regs -> 3 CTAs/SM):
//   half h: S(16x32) = Q.K'^T; delta = expm1(S) via bf16x2 HFMA2 (output IS the
//   bf16 A-fragment); PV k-steps 2h,2h+1: OUT(16x40) += delta.[V|ones].
//   out = (vsum + OUT) / (4096 + lsum), lsum = OUT col 32.
// ---------------------------------------------------------------------------
__global__ void __launch_bounds__(256, 3) attn_mma_kernel()
{
    __shared__ __align__(16) unsigned char sbuf[4][TILEB];  // 40 KB

    const int tid  = threadIdx.x;
    const int lane = tid & 31;
    const int w    = tid >> 5;
    const int g    = lane >> 2;
    const int tg   = lane & 3;

    const int bh = blockIdx.y;
    const int b = bh >> 2, h = bh & 3;
    const int i0 = blockIdx.x * 128 + w * 16;

    const float* qb = g_qkv + ((size_t)(b * OQKV_) + h * DH_) * N_;
    const unsigned char* pk = g_pack + (size_t)bh * 64 * TILEB;

    // Q fragments (2 k-steps of 16), loaded once
    uint32_t qa[2][4];
    #pragma unroll
    for (int ks = 0; ks < 2; ks++) {
        #pragma unroll
        for (int rr = 0; rr < 4; rr++) {
            int r = i0 + g + ((rr & 1) ? 8 : 0);
            int d = ks * 16 + 2 * tg + ((rr >> 1) ? 8 : 0);
            qa[ks][rr] = packbf2(qb[(size_t)d * N_ + r], qb[(size_t)(d + 1) * N_ + r]);
        }
    }

    const __nv_bfloat162 C6  = __float2bfloat162_rn(0.16666667f);
    const __nv_bfloat162 C5  = __float2bfloat162_rn(0.5f);
    const __nv_bfloat162 ONE = __float2bfloat162_rn(1.0f);

    auto issue = [&](int ti) {
        const unsigned char* src = pk + (size_t)ti * TILEB;
        uint32_t dst = smem_to_u32(sbuf[ti & 3]);
        cp_async16(dst + tid * 16, src + tid * 16);
        cp_async16(dst + (tid + 256) * 16, src + (tid + 256) * 16);
        if (tid < 128) cp_async16(dst + (tid + 512) * 16, src + (tid + 512) * 16);
        asm volatile("cp.async.commit_group;" ::: "memory");
    };

    float oacc[5][4] = {};

    issue(0); issue(1); issue(2);

    for (int ti = 0; ti < 64; ti++) {
        asm volatile("cp.async.wait_group 2;" ::: "memory");
        __syncthreads();
        if (ti + 3 < 64) issue(ti + 3);   // into buf consumed at ti-1, safe post-sync

        const uint32_t smK = smem_to_u32(sbuf[ti & 3]);
        const uint32_t smV = smK + 5120;

        #pragma unroll
        for (int hf = 0; hf < 2; hf++) {
            // S half: 4 n-blocks of 8 j, 2 k-steps
            float sc[4][4];
            #pragma unroll
            for (int q4 = 0; q4 < 4; q4++) {
                sc[q4][0] = sc[q4][1] = sc[q4][2] = sc[q4][3] = 0.0f;
                uint32_t r0, r1, r2, r3;
                uint32_t jrow = (uint32_t)((hf * 4 + q4) * 8 + (lane & 7));
                ldsm4(r0, r1, r2, r3, smK + jrow * TPITCH + (uint32_t)(lane >> 3) * 16u);
                mma_bf16(sc[q4], qa[0][0], qa[0][1], qa[0][2], qa[0][3], r0, r1);
                mma_bf16(sc[q4], qa[1][0], qa[1][1], qa[1][2], qa[1][3], r2, r3);
            }

            // delta = expm1(s): bf16x2 poly, result IS the A-fragment word
            uint32_t pa[2][4];
            #pragma unroll
            for (int q4 = 0; q4 < 4; q4++) {
                __nv_bfloat162 s01 = __floats2bfloat162_rn(sc[q4][0], sc[q4][1]);
                __nv_bfloat162 s23 = __floats2bfloat162_rn(sc[q4][2], sc[q4][3]);
                __nv_bfloat162 t01 = __hfma2(s01, C6, C5);
                __nv_bfloat162 t23 = __hfma2(s23, C6, C5);
                t01 = __hfma2(s01, t01, ONE);
                t23 = __hfma2(s23, t23, ONE);
                pa[q4 >> 1][(q4 & 1) * 2 + 0] = bf2u(__hmul2(s01, t01));
                pa[q4 >> 1][(q4 & 1) * 2 + 1] = bf2u(__hmul2(s23, t23));
            }

            // PV k-steps 2hf, 2hf+1 over 5 d-blocks (block 4 = ones column)
            #pragma unroll
            for (int nbd = 0; nbd < 5; nbd++) {
                uint32_t v0, v1, v2, v3;
                ldsm4t(v0, v1, v2, v3,
                       smV + (uint32_t)(hf * 32 + lane) * TPITCH + (uint32_t)nbd * 16u);
                mma_bf16(oacc[nbd], pa[0][0], pa[0][1], pa[0][2], pa[0][3], v0, v1);
                mma_bf16(oacc[nbd], pa[1][0], pa[1][1], pa[1][2], pa[1][3], v2, v3);
            }
        }
    }

    // lsum lives in OUT col 32 (block 4, col 0) owned by tg=0 lanes
    float lA = __shfl_sync(0xffffffffu, oacc[4][0], lane & ~3);
    float lB = __shfl_sync(0xffffffffu, oacc[4][2], lane & ~3);
    const float rA = 1.0f / (4096.0f + lA);
    const float rB = 1.0f / (4096.0f + lB);

    // out = (vsum + OUT) / denom, channel-major
    const int chan0 = b * HID_ + h * DH_;
    const int iA = i0 + g, iB = i0 + g + 8;
    #pragma unroll
    for (int nbd = 0; nbd < 4; nbd++) {
        int d0 = nbd * 8 + 2 * tg;
        float vs0 = g_vsum[chan0 + d0];
        float vs1 = g_vsum[chan0 + d0 + 1];
        g_oimg[(size_t)(chan0 + d0)     * N_ + iA] = (vs0 + oacc[nbd][0]) * rA;
        g_oimg[(size_t)(chan0 + d0 + 1) * N_ + iA] = (vs1 + oacc[nbd][1]) * rA;
        g_oimg[(size_t)(chan0 + d0)     * N_ + iB] = (vs0 + oacc[nbd][2]) * rB;
        g_oimg[(size_t)(chan0 + d0 + 1) * N_ + iB] = (vs1 + oacc[nbd][3]) * rB;
    }
}

// ---------------------------------------------------------------------------
extern "C" void kernel_launch(void* const* d_in, const int* in_sizes, int n_in,
                              void* d_out, int out_size)
{
    (void)in_sizes; (void)n_in; (void)out_size;
    const float* x     = (const float*)d_in[0];
    const float* w_qkv = (const float*)d_in[1];
    const float* w_out = (const float*)d_in[2];
    const float* b_out = (const float*)d_in[3];
    float* y = (float*)d_out;

    float *qkv_p, *oimg_p;
    cudaGetSymbolAddress((void**)&qkv_p,  g_qkv);
    cudaGetSymbolAddress((void**)&oimg_p, g_oimg);

    gemm_wx<<<dim3(N_/128, OQKV_/128, B_), 256>>>(w_qkv, x, nullptr, qkv_p,
                                                  OQKV_, CIN_, N_);
    norm_kernel<<<B_ * HID_, 256>>>();
    pack_kernel<<<dim3(64, 16), 256>>>();
    attn_mma_kernel<<<dim3(N_/128, B_ * HEADS_), 256>>>();
    gemm_wx<<<dim3(N_/128, CIN_/128, B_), 256>>>(w_out, oimg_p, b_out, y,
                                                 CIN_, HID_, N_);
}

// round 6
// speedup vs baseline: 7.3906x; 1.2725x over previous
#include <cuda_runtime.h>
#include <cuda_bf16.h>
#include <math.h>
#include <cstdint>

#define B_     4
#define CIN_   256
#define N_     4096
#define HEADS_ 4
#define DH_    32
#define HID_   128
#define OQKV_  384
#define TPITCH 80u
#define TILEB  10240

// Scratch (allocation-free rule: __device__ globals)
__device__ float g_qkv[B_ * OQKV_ * N_];    // [b][o][n]: q 0..127, k 128..255, v 256..383
__device__ float g_scale[B_ * HID_];        // 10 / (||q_d|| ||k_d||)
__device__ float g_vsum[B_ * HID_];         // sum_j v[d][j]
__device__ float g_oimg[B_ * HID_ * N_];    // attention out, channel-major
__device__ __align__(16) unsigned char g_pack[16 * 64 * TILEB];  // attn K'/V bf16 tiles
// split-precision operands for the projection GEMMs
__device__ __align__(16) __nv_bfloat16 g_xh[B_ * CIN_ * N_];
__device__ __align__(16) __nv_bfloat16 g_xl[B_ * CIN_ * N_];
__device__ __align__(16) __nv_bfloat16 g_oh[B_ * HID_ * N_];
__device__ __align__(16) __nv_bfloat16 g_ol[B_ * HID_ * N_];
// W hi/lo packed into cp.async-ready 64m x 32k tiles (80B pitch rows, hi|lo)
__device__ __align__(16) unsigned char g_wp1[6 * 8 * TILEB];   // w_qkv: 384x256
__device__ __align__(16) unsigned char g_wp2[4 * 4 * TILEB];   // w_out: 256x128

// ---------------------------------------------------------------------------
// helpers
// ---------------------------------------------------------------------------
__device__ __forceinline__ uint32_t smem_to_u32(const void* p) {
    uint32_t a;
    asm("{ .reg .u64 t; cvta.to.shared.u64 t, %1; cvt.u32.u64 %0, t; }" : "=r"(a) : "l"(p));
    return a;
}

__device__ __forceinline__ void mma_bf16(float c[4],
                                         uint32_t a0, uint32_t a1, uint32_t a2, uint32_t a3,
                                         uint32_t b0, uint32_t b1) {
    asm volatile(
        "mma.sync.aligned.m16n8k16.row.col.f32.bf16.bf16.f32 "
        "{%0,%1,%2,%3}, {%4,%5,%6,%7}, {%8,%9}, {%0,%1,%2,%3};"
        : "+f"(c[0]), "+f"(c[1]), "+f"(c[2]), "+f"(c[3])
        : "r"(a0), "r"(a1), "r"(a2), "r"(a3), "r"(b0), "r"(b1));
}

__device__ __forceinline__ void ldsm4(uint32_t& r0, uint32_t& r1, uint32_t& r2, uint32_t& r3,
                                      uint32_t addr) {
    asm volatile("ldmatrix.sync.aligned.m8n8.x4.shared.b16 {%0,%1,%2,%3}, [%4];"
                 : "=r"(r0), "=r"(r1), "=r"(r2), "=r"(r3) : "r"(addr));
}
__device__ __forceinline__ void ldsm4t(uint32_t& r0, uint32_t& r1, uint32_t& r2, uint32_t& r3,
                                       uint32_t addr) {
    asm volatile("ldmatrix.sync.aligned.m8n8.x4.trans.shared.b16 {%0,%1,%2,%3}, [%4];"
                 : "=r"(r0), "=r"(r1), "=r"(r2), "=r"(r3) : "r"(addr));
}

__device__ __forceinline__ uint32_t packbf2(float lo, float hi) {
    __nv_bfloat162 p = __floats2bfloat162_rn(lo, hi);
    return *reinterpret_cast<uint32_t*>(&p);
}
__device__ __forceinline__ uint32_t bf2u(__nv_bfloat162 p) {
    return *reinterpret_cast<uint32_t*>(&p);
}

__device__ __forceinline__ void cp_async16(uint32_t s, const void* g) {
    asm volatile("cp.async.cg.shared.global [%0], [%1], 16;" :: "r"(s), "l"(g));
}

// ---------------------------------------------------------------------------
// convert_split: fp32 -> (bf16 hi, bf16 lo = x - hi), 4 elems/thread
// ---------------------------------------------------------------------------
__global__ void __launch_bounds__(256) convert_split(
    const float* __restrict__ src, __nv_bfloat16* __restrict__ hi,
    __nv_bfloat16* __restrict__ lo, int n4)
{
    int idx = blockIdx.x * 256 + threadIdx.x;
    if (idx >= n4) return;
    float4 f = reinterpret_cast<const float4*>(src)[idx];
    __nv_bfloat16 h0 = __float2bfloat16_rn(f.x);
    __nv_bfloat16 h1 = __float2bfloat16_rn(f.y);
    __nv_bfloat16 h2 = __float2bfloat16_rn(f.z);
    __nv_bfloat16 h3 = __float2bfloat16_rn(f.w);
    uint2 hw, lw;
    __nv_bfloat162 p01; p01.x = h0; p01.y = h1;
    __nv_bfloat162 p23; p23.x = h2; p23.y = h3;
    hw.x = bf2u(p01); hw.y = bf2u(p23);
    lw.x = packbf2(f.x - __bfloat162float(h0), f.y - __bfloat162float(h1));
    lw.y = packbf2(f.z - __bfloat162float(h2), f.w - __bfloat162float(h3));
    reinterpret_cast<uint2*>(hi)[idx] = hw;
    reinterpret_cast<uint2*>(lo)[idx] = lw;
}

// ---------------------------------------------------------------------------
// convert_w: W fp32 [M][K] -> packed tiles [mt][s][ hi 64x80B | lo 64x80B ]
// grid (M/64, K/32), 256 threads; thread handles 8 k of one m row.
// ---------------------------------------------------------------------------
__global__ void __launch_bounds__(256) convert_w(
    const float* __restrict__ W, unsigned char* __restrict__ dst, int M, int K)
{
    const int mt = blockIdx.x, s = blockIdx.y;
    const int m  = threadIdx.x & 63;
    const int kg = (threadIdx.x >> 6) * 8;
    unsigned char* base = dst + ((size_t)mt * (K >> 5) + s) * TILEB;
    const float* wrow = W + (size_t)(mt * 64 + m) * K + s * 32 + kg;

    #pragma unroll
    for (int p = 0; p < 4; p++) {
        float w0 = wrow[2 * p], w1 = wrow[2 * p + 1];
        __nv_bfloat16 h0 = __float2bfloat16_rn(w0);
        __nv_bfloat16 h1 = __float2bfloat16_rn(w1);
        __nv_bfloat162 ph; ph.x = h0; ph.y = h1;
        int k = kg + 2 * p;
        uint32_t off = (uint32_t)m * TPITCH + (uint32_t)((k >> 3) * 16 + (k & 7) * 2);
        *reinterpret_cast<uint32_t*>(base + off) = bf2u(ph);
        *reinterpret_cast<uint32_t*>(base + 5120 + off) =
            packbf2(w0 - __bfloat162float(h0), w1 - __bfloat162float(h1));
    }
}

// ---------------------------------------------------------------------------
// Split-bf16 tensor-core GEMM: out[b][m][n] = sum_k W[m][k] X[b][k][n] (+bias)
// = Xh.Wh + Xl.Wh + Xh.Wl  (Xl.Wl dropped: 2^-18 relative).
// CTA: 256 thr, n-tile 64, m-tile 64; warp (wn 0..3 x wm 0..1) = 16n x 32m.
// smem stage: XH 4096 (32k x 64n, pitch128, chunk^k swizzle) + XL 4096
//             + W hi|lo 10240 (64m x 32k, 80B pitch)  -> 2 stages = 36 KB.
// ---------------------------------------------------------------------------
__global__ void __launch_bounds__(256) gemm_mma(
    const __nv_bfloat16* __restrict__ Xh, const __nv_bfloat16* __restrict__ Xl,
    const unsigned char* __restrict__ Wp, const float* __restrict__ bias,
    float* __restrict__ out, int M, int K)
{
    __shared__ __align__(16) unsigned char smem[2][18432];

    const int tid = threadIdx.x, lane = tid & 31, w = tid >> 5;
    const int wn = w & 3, wm = w >> 2;
    const int g = lane >> 2, tg = lane & 3;
    const int n0 = blockIdx.x * 64, mt = blockIdx.y, b = blockIdx.z;
    const int nstages = K >> 5;

    const __nv_bfloat16* xh = Xh + (size_t)b * K * N_ + n0;
    const __nv_bfloat16* xl = Xl + (size_t)b * K * N_ + n0;
    const unsigned char* wp = Wp + (size_t)mt * nstages * TILEB;

    const int ck = tid >> 3, cc = tid & 7;              // X chunk (k row, n chunk)
    const uint32_t xdst = (uint32_t)(ck * 128 + ((cc ^ (ck & 7)) * 16));

    auto issue = [&](int s) {
        uint32_t dst = smem_to_u32(smem[s & 1]);
        const char* sh = (const char*)(xh + (size_t)(s * 32 + ck) * N_) + cc * 16;
        const char* sl = (const char*)(xl + (size_t)(s * 32 + ck) * N_) + cc * 16;
        cp_async16(dst + xdst, sh);
        cp_async16(dst + 4096 + xdst, sl);
        const unsigned char* ws = wp + (size_t)s * TILEB;
        cp_async16(dst + 8192 + tid * 16, ws + tid * 16);
        cp_async16(dst + 8192 + (tid + 256) * 16, ws + (tid + 256) * 16);
        if (tid < 128) cp_async16(dst + 8192 + (tid + 512) * 16, ws + (tid + 512) * 16);
        asm volatile("cp.async.commit_group;" ::: "memory");
    };

    float acc[4][4] = {};

    issue(0);
    for (int s = 0; s < nstages; s++) {
        if (s + 1 < nstages) {
            issue(s + 1);
            asm volatile("cp.async.wait_group 1;" ::: "memory");
        } else {
            asm volatile("cp.async.wait_group 0;" ::: "memory");
        }
        __syncthreads();

        const uint32_t smX = smem_to_u32(smem[s & 1]);
        const uint32_t smW = smX + 8192;

        // A fragments (X^T, 16n x 16k per k-step) via trans ldsm on [k][n] tile
        uint32_t Ah[2][4], Al[2][4];
        const int arow = ((lane & 16) >> 1) + (lane & 7);       // k row within block
        const int alog = wn * 2 + ((lane >> 3) & 1);            // logical n chunk
        #pragma unroll
        for (int ks = 0; ks < 2; ks++) {
            int kr = ks * 16 + arow;
            uint32_t aoff = (uint32_t)(kr * 128 + ((alog ^ (kr & 7)) * 16));
            ldsm4t(Ah[ks][0], Ah[ks][1], Ah[ks][2], Ah[ks][3], smX + aoff);
            ldsm4t(Al[ks][0], Al[ks][1], Al[ks][2], Al[ks][3], smX + 4096 + aoff);
        }

        #pragma unroll
        for (int mb = 0; mb < 4; mb++) {
            uint32_t waddr = smW + (uint32_t)((wm * 32 + mb * 8 + (lane & 7)) * TPITCH
                                              + (lane >> 3) * 16);
            uint32_t bh0, bh1, bh2, bh3, bl0, bl1, bl2, bl3;
            ldsm4(bh0, bh1, bh2, bh3, waddr);
            ldsm4(bl0, bl1, bl2, bl3, waddr + 5120);
            mma_bf16(acc[mb], Ah[0][0], Ah[0][1], Ah[0][2], Ah[0][3], bh0, bh1);
            mma_bf16(acc[mb], Ah[1][0], Ah[1][1], Ah[1][2], Ah[1][3], bh2, bh3);
            mma_bf16(acc[mb], Al[0][0], Al[0][1], Al[0][2], Al[0][3], bh0, bh1);
            mma_bf16(acc[mb], Al[1][0], Al[1][1], Al[1][2], Al[1][3], bh2, bh3);
            mma_bf16(acc[mb], Ah[0][0], Ah[0][1], Ah[0][2], Ah[0][3], bl0, bl1);
            mma_bf16(acc[mb], Ah[1][0], Ah[1][1], Ah[1][2], Ah[1][3], bl2, bl3);
        }
        __syncthreads();
    }

    const int nA = n0 + wn * 16 + g, nB = nA + 8;
    #pragma unroll
    for (int mb = 0; mb < 4; mb++) {
        int m = mt * 64 + wm * 32 + mb * 8 + 2 * tg;
        float bv0 = bias ? bias[m] : 0.0f;
        float bv1 = bias ? bias[m + 1] : 0.0f;
        float* o0 = out + ((size_t)b * M + m) * N_;
        float* o1 = o0 + N_;
        o0[nA] = acc[mb][0] + bv0;
        o1[nA] = acc[mb][1] + bv1;
        o0[nB] = acc[mb][2] + bv0;
        o1[nB] = acc[mb][3] + bv1;
    }
}

// ---------------------------------------------------------------------------
// Per (b,hd): q,k row norms (-> folded scale) and v row sum.
// ---------------------------------------------------------------------------
__global__ void __launch_bounds__(256) norm_kernel()
{
    const int idx = blockIdx.x;
    const int b  = idx >> 7;
    const int hd = idx & 127;
    const float* q = g_qkv + ((size_t)(b * OQKV_ + hd)) * N_;
    const float* k = q + (size_t)HID_ * N_;
    const float* v = q + (size_t)(2 * HID_) * N_;

    float sq = 0.f, sk = 0.f, sv = 0.f;
    for (int i = threadIdx.x; i < N_; i += 256) {
        float a = q[i]; sq += a * a;
        float c = k[i]; sk += c * c;
        sv += v[i];
    }
    __shared__ float rq[256], rk[256], rv[256];
    rq[threadIdx.x] = sq; rk[threadIdx.x] = sk; rv[threadIdx.x] = sv;
    __syncthreads();
    for (int s = 128; s > 0; s >>= 1) {
        if (threadIdx.x < s) {
            rq[threadIdx.x] += rq[threadIdx.x + s];
            rk[threadIdx.x] += rk[threadIdx.x + s];
            rv[threadIdx.x] += rv[threadIdx.x + s];
        }
        __syncthreads();
    }
    if (threadIdx.x == 0) {
        float nq = fmaxf(sqrtf(rq[0]), 1e-12f);
        float nk = fmaxf(sqrtf(rk[0]), 1e-12f);
        g_scale[idx] = 10.0f / (nq * nk);
        g_vsum[idx]  = rv[0];
    }
}

// ---------------------------------------------------------------------------
// Pack K' (k * folded scale) and V into bf16 LDSM-ready tiles.
// ---------------------------------------------------------------------------
__global__ void __launch_bounds__(256) pack_kernel()
{
    const int bh = blockIdx.y, ti = blockIdx.x;
    const int b = bh >> 2, h = bh & 3;
    const float* kb = g_qkv + ((size_t)(b * OQKV_) + HID_ + h * DH_) * N_;
    const float* vb = kb + (size_t)HID_ * N_;

    const int j  = threadIdx.x & 63;
    const int dg = threadIdx.x >> 6;
    const int jt = ti * 64;
    unsigned char* out = g_pack + ((size_t)bh * 64 + ti) * TILEB;

    uint32_t kw[4], vw[4];
    #pragma unroll
    for (int p = 0; p < 4; p++) {
        int d = dg * 8 + 2 * p;
        float c0 = g_scale[bh * DH_ + d];
        float c1 = g_scale[bh * DH_ + d + 1];
        float k0 = kb[(size_t)d * N_ + jt + j];
        float k1 = kb[(size_t)(d + 1) * N_ + jt + j];
        kw[p] = packbf2(k0 * c0, k1 * c1);
        vw[p] = packbf2(vb[(size_t)d * N_ + jt + j], vb[(size_t)(d + 1) * N_ + jt + j]);
    }
    *(uint4*)(out + j * TPITCH + dg * 16)        = make_uint4(kw[0], kw[1], kw[2], kw[3]);
    *(uint4*)(out + 5120 + j * TPITCH + dg * 16) = make_uint4(vw[0], vw[1], vw[2], vw[3]);

    if (threadIdx.x < 64) {
        *(uint4*)(out + threadIdx.x * TPITCH + 64) = make_uint4(0u, 0u, 0u, 0u);
    } else if (threadIdx.x < 128) {
        int jj = threadIdx.x - 64;  // V pad: d=32 column of ones (lsum via MMA)
        *(uint4*)(out + 5120 + jj * TPITCH + 64) = make_uint4(0x00003F80u, 0u, 0u, 0u);
    }
}

// ---------------------------------------------------------------------------
// bf16 mma.sync flash attention (unchanged from round 5; 121 us measured).
// ---------------------------------------------------------------------------
__global__ void __launch_bounds__(256, 3) attn_mma_kernel()
{
    __shared__ __align__(16) unsigned char sbuf[4][TILEB];  // 40 KB

    const int tid  = threadIdx.x;
    const int lane = tid & 31;
    const int w    = tid >> 5;
    const int g    = lane >> 2;
    const int tg   = lane & 3;

    const int bh = blockIdx.y;
    const int b = bh >> 2, h = bh & 3;
    const int i0 = blockIdx.x * 128 + w * 16;

    const float* qb = g_qkv + ((size_t)(b * OQKV_) + h * DH_) * N_;
    const unsigned char* pk = g_pack + (size_t)bh * 64 * TILEB;

    uint32_t qa[2][4];
    #pragma unroll
    for (int ks = 0; ks < 2; ks++) {
        #pragma unroll
        for (int rr = 0; rr < 4; rr++) {
            int r = i0 + g + ((rr & 1) ? 8 : 0);
            int d = ks * 16 + 2 * tg + ((rr >> 1) ? 8 : 0);
            qa[ks][rr] = packbf2(qb[(size_t)d * N_ + r], qb[(size_t)(d + 1) * N_ + r]);
        }
    }

    const __nv_bfloat162 C6  = __float2bfloat162_rn(0.16666667f);
    const __nv_bfloat162 C5  = __float2bfloat162_rn(0.5f);
    const __nv_bfloat162 ONE = __float2bfloat162_rn(1.0f);

    auto issue = [&](int ti) {
        const unsigned char* src = pk + (size_t)ti * TILEB;
        uint32_t dst = smem_to_u32(sbuf[ti & 3]);
        cp_async16(dst + tid * 16, src + tid * 16);
        cp_async16(dst + (tid + 256) * 16, src + (tid + 256) * 16);
        if (tid < 128) cp_async16(dst + (tid + 512) * 16, src + (tid + 512) * 16);
        asm volatile("cp.async.commit_group;" ::: "memory");
    };

    float oacc[5][4] = {};

    issue(0); issue(1); issue(2);

    for (int ti = 0; ti < 64; ti++) {
        asm volatile("cp.async.wait_group 2;" ::: "memory");
        __syncthreads();
        if (ti + 3 < 64) issue(ti + 3);

        const uint32_t smK = smem_to_u32(sbuf[ti & 3]);
        const uint32_t smV = smK + 5120;

        #pragma unroll
        for (int hf = 0; hf < 2; hf++) {
            float sc[4][4];
            #pragma unroll
            for (int q4 = 0; q4 < 4; q4++) {
                sc[q4][0] = sc[q4][1] = sc[q4][2] = sc[q4][3] = 0.0f;
                uint32_t r0, r1, r2, r3;
                uint32_t jrow = (uint32_t)((hf * 4 + q4) * 8 + (lane & 7));
                ldsm4(r0, r1, r2, r3, smK + jrow * TPITCH + (uint32_t)(lane >> 3) * 16u);
                mma_bf16(sc[q4], qa[0][0], qa[0][1], qa[0][2], qa[0][3], r0, r1);
                mma_bf16(sc[q4], qa[1][0], qa[1][1], qa[1][2], qa[1][3], r2, r3);
            }

            uint32_t pa[2][4];
            #pragma unroll
            for (int q4 = 0; q4 < 4; q4++) {
                __nv_bfloat162 s01 = __floats2bfloat162_rn(sc[q4][0], sc[q4][1]);
                __nv_bfloat162 s23 = __floats2bfloat162_rn(sc[q4][2], sc[q4][3]);
                __nv_bfloat162 t01 = __hfma2(s01, C6, C5);
                __nv_bfloat162 t23 = __hfma2(s23, C6, C5);
                t01 = __hfma2(s01, t01, ONE);
                t23 = __hfma2(s23, t23, ONE);
                pa[q4 >> 1][(q4 & 1) * 2 + 0] = bf2u(__hmul2(s01, t01));
                pa[q4 >> 1][(q4 & 1) * 2 + 1] = bf2u(__hmul2(s23, t23));
            }

            #pragma unroll
            for (int nbd = 0; nbd < 5; nbd++) {
                uint32_t v0, v1, v2, v3;
                ldsm4t(v0, v1, v2, v3,
                       smV + (uint32_t)(hf * 32 + lane) * TPITCH + (uint32_t)nbd * 16u);
                mma_bf16(oacc[nbd], pa[0][0], pa[0][1], pa[0][2], pa[0][3], v0, v1);
                mma_bf16(oacc[nbd], pa[1][0], pa[1][1], pa[1][2], pa[1][3], v2, v3);
            }
        }
    }

    float lA = __shfl_sync(0xffffffffu, oacc[4][0], lane & ~3);
    float lB = __shfl_sync(0xffffffffu, oacc[4][2], lane & ~3);
    const float rA = 1.0f / (4096.0f + lA);
    const float rB = 1.0f / (4096.0f + lB);

    const int chan0 = b * HID_ + h * DH_;
    const int iA = i0 + g, iB = i0 + g + 8;
    #pragma unroll
    for (int nbd = 0; nbd < 4; nbd++) {
        int d0 = nbd * 8 + 2 * tg;
        float vs0 = g_vsum[chan0 + d0];
        float vs1 = g_vsum[chan0 + d0 + 1];
        g_oimg[(size_t)(chan0 + d0)     * N_ + iA] = (vs0 + oacc[nbd][0]) * rA;
        g_oimg[(size_t)(chan0 + d0 + 1) * N_ + iA] = (vs1 + oacc[nbd][1]) * rA;
        g_oimg[(size_t)(chan0 + d0)     * N_ + iB] = (vs0 + oacc[nbd][2]) * rB;
        g_oimg[(size_t)(chan0 + d0 + 1) * N_ + iB] = (vs1 + oacc[nbd][3]) * rB;
    }
}

// ---------------------------------------------------------------------------
extern "C" void kernel_launch(void* const* d_in, const int* in_sizes, int n_in,
                              void* d_out, int out_size)
{
    (void)in_sizes; (void)n_in; (void)out_size;
    const float* x     = (const float*)d_in[0];
    const float* w_qkv = (const float*)d_in[1];
    const float* w_out = (const float*)d_in[2];
    const float* b_out = (const float*)d_in[3];
    float* y = (float*)d_out;

    float *qkv_p, *oimg_p;
    __nv_bfloat16 *xh_p, *xl_p, *oh_p, *ol_p;
    unsigned char *wp1_p, *wp2_p;
    cudaGetSymbolAddress((void**)&qkv_p,  g_qkv);
    cudaGetSymbolAddress((void**)&oimg_p, g_oimg);
    cudaGetSymbolAddress((void**)&xh_p,   g_xh);
    cudaGetSymbolAddress((void**)&xl_p,   g_xl);
    cudaGetSymbolAddress((void**)&oh_p,   g_oh);
    cudaGetSymbolAddress((void**)&ol_p,   g_ol);
    cudaGetSymbolAddress((void**)&wp1_p,  g_wp1);
    cudaGetSymbolAddress((void**)&wp2_p,  g_wp2);

    // split-convert inputs once
    convert_split<<<(B_ * CIN_ * N_) / 1024, 256>>>(x, xh_p, xl_p, (B_ * CIN_ * N_) / 4);
    convert_w<<<dim3(OQKV_ / 64, CIN_ / 32), 256>>>(w_qkv, wp1_p, OQKV_, CIN_);
    convert_w<<<dim3(CIN_ / 64, HID_ / 32), 256>>>(w_out, wp2_p, CIN_, HID_);

    // 1) QKV projection on tensor cores
    gemm_mma<<<dim3(N_ / 64, OQKV_ / 64, B_), 256>>>(xh_p, xl_p, wp1_p, nullptr,
                                                     qkv_p, OQKV_, CIN_);
    // 2) norms + folded scale, 3) bf16 tile pack, 4) attention
    norm_kernel<<<B_ * HID_, 256>>>();
    pack_kernel<<<dim3(64, 16), 256>>>();
    attn_mma_kernel<<<dim3(N_ / 128, B_ * HEADS_), 256>>>();

    // 5) output projection on tensor cores
    convert_split<<<(B_ * HID_ * N_) / 1024, 256>>>(oimg_p, oh_p, ol_p,
                                                    (B_ * HID_ * N_) / 4);
    gemm_mma<<<dim3(N_ / 64, CIN_ / 64, B_), 256>>>(oh_p, ol_p, wp2_p, b_out,
                                                    y, CIN_, HID_);
}